// round 1
// baseline (speedup 1.0000x reference)
#include <cuda_runtime.h>

#define NB   16
#define WIN  128
#define KF   256
#define EMB  256

// ---------------- device scratch (allocation-free rule: __device__ globals) ---
__device__ float g_UI[NB * KF * EMB];   // hi + lin_b   (4 MB)
__device__ float g_HJ[NB * KF * EMB];   // hj           (4 MB)
__device__ float g_AI[NB * KF];         // 0.2 * dot(UI_row, a)
__device__ float g_AJ[NB * KF];         // 0.2 * dot(HJ_row, a)
__device__ float g_ATT[NB * KF * KF];   // softmaxed attention (4 MB)

// ============================================================================
// Kernel A: UI[b,k,e] = sum_w x[b,w,k]*lin_w[e,w] + lin_b[e]
//           HJ[b,k,e] = sum_w x[b,w,k]*lin_w[e,WIN+w]
// Tile: 64 k x 64 e, full w=128 in smem. 256 threads, 4x4 micro, two outputs.
// ============================================================================
__global__ __launch_bounds__(256, 1)
void gemmA(const float* __restrict__ x, const float* __restrict__ lw,
           const float* __restrict__ lb)
{
    extern __shared__ float sm[];
    float* sX  = sm;                 // [128][64]
    float* sW1 = sX  + 128 * 64;     // [64][128]
    float* sW2 = sW1 + 64 * 128;     // [64][128]

    const int b  = blockIdx.z;
    const int kt = blockIdx.y * 64;
    const int et = blockIdx.x * 64;
    const int t  = threadIdx.x;

    const float* xb = x + (size_t)b * WIN * KF;
    for (int idx = t; idx < 128 * 64; idx += 256) {
        int w = idx >> 6, kk = idx & 63;
        sX[idx] = xb[w * KF + kt + kk];
    }
    for (int idx = t; idx < 64 * 128; idx += 256) {
        int ee = idx >> 7, w = idx & 127;
        sW1[idx] = lw[(et + ee) * (2 * WIN) + w];
        sW2[idx] = lw[(et + ee) * (2 * WIN) + WIN + w];
    }
    __syncthreads();

    const int tk = t & 15;   // k group
    const int te = t >> 4;   // e group
    float accI[4][4] = {}, accJ[4][4] = {};

    #pragma unroll 2
    for (int w = 0; w < 128; ++w) {
        float xv[4], w1[4], w2[4];
        #pragma unroll
        for (int ii = 0; ii < 4; ++ii) xv[ii] = sX[w * 64 + tk + ii * 16];
        #pragma unroll
        for (int jj = 0; jj < 4; ++jj) {
            w1[jj] = sW1[(te + jj * 16) * 128 + w];
            w2[jj] = sW2[(te + jj * 16) * 128 + w];
        }
        #pragma unroll
        for (int ii = 0; ii < 4; ++ii)
            #pragma unroll
            for (int jj = 0; jj < 4; ++jj) {
                accI[ii][jj] += xv[ii] * w1[jj];
                accJ[ii][jj] += xv[ii] * w2[jj];
            }
    }

    #pragma unroll
    for (int ii = 0; ii < 4; ++ii) {
        int k = kt + tk + ii * 16;
        #pragma unroll
        for (int jj = 0; jj < 4; ++jj) {
            int e = et + te + jj * 16;
            size_t o = ((size_t)b * KF + k) * EMB + e;
            g_UI[o] = accI[ii][jj] + lb[e];
            g_HJ[o] = accJ[ii][jj];
        }
    }
}

// ============================================================================
// Kernel A2: AI[b,k] = 0.2*dot(UI[b,k,:],a); AJ[b,k] = 0.2*dot(HJ[b,k,:],a)
// One warp per row.
// ============================================================================
__global__ __launch_bounds__(256, 4)
void dotAK(const float* __restrict__ a)
{
    int gw   = (blockIdx.x * blockDim.x + threadIdx.x) >> 5;
    int lane = threadIdx.x & 31;
    int which = gw / (NB * KF);
    int rk    = gw - which * (NB * KF);
    const float* row = (which ? g_HJ : g_UI) + (size_t)rk * EMB;
    float s = 0.f;
    #pragma unroll
    for (int q = 0; q < 8; ++q) s += row[lane + q * 32] * a[lane + q * 32];
    #pragma unroll
    for (int off = 16; off; off >>= 1) s += __shfl_xor_sync(0xffffffffu, s, off);
    if (lane == 0) (which ? g_AJ : g_AI)[rk] = 0.2f * s;
}

// ============================================================================
// Kernel B: e[b,i,j] = AI[i] + AJ[j] + sum_e relu(UI[i,e]+HJ[j,e])*0.8*a[e]
//                      + attn_bias[i,j]; then row softmax over j -> g_ATT.
// Block: (b, i-tile of 32). j tiled by 64. 256 threads, 2(i) x 4(j) micro.
// ============================================================================
__global__ __launch_bounds__(256, 1)
void kernB(const float* __restrict__ a, const float* __restrict__ ab)
{
    extern __shared__ float sm[];
    float* sUI = sm;                   // [32][257]
    float* sHJ = sUI + 32 * 257;       // [64][257]
    float* sE  = sHJ + 64 * 257;       // [32][257]
    float* sA8 = sE  + 32 * 257;       // [256]
    float* sAI = sA8 + 256;            // [32]
    float* sAJ = sAI + 32;             // [64]

    const int b  = blockIdx.y;
    const int i0 = blockIdx.x * 32;
    const int t  = threadIdx.x;

    for (int idx = t; idx < 32 * EMB; idx += 256) {
        int r = idx >> 8, e = idx & 255;
        sUI[r * 257 + e] = g_UI[((size_t)b * KF + i0 + r) * EMB + e];
    }
    sA8[t] = 0.8f * a[t];
    if (t < 32) sAI[t] = g_AI[b * KF + i0 + t];

    const int ti = t & 15;   // i group: rows ti, ti+16
    const int tj = t >> 4;   // j group: cols tj*4 .. tj*4+3

    for (int jt = 0; jt < 4; ++jt) {
        __syncthreads();     // protect sHJ reuse + sUI ready on first pass
        const int j0 = jt * 64;
        for (int idx = t; idx < 64 * EMB; idx += 256) {
            int r = idx >> 8, e = idx & 255;
            sHJ[r * 257 + e] = g_HJ[((size_t)b * KF + j0 + r) * EMB + e];
        }
        if (t < 64) sAJ[t] = g_AJ[b * KF + j0 + t];
        __syncthreads();

        float acc0[4] = {}, acc1[4] = {};
        const float* u0p = sUI + ti * 257;
        const float* u1p = sUI + (ti + 16) * 257;
        #pragma unroll 4
        for (int e = 0; e < EMB; ++e) {
            float ae = sA8[e];
            float u0 = u0p[e];
            float u1 = u1p[e];
            #pragma unroll
            for (int q = 0; q < 4; ++q) {
                float v = sHJ[(tj * 4 + q) * 257 + e];
                acc0[q] += fmaxf(u0 + v, 0.f) * ae;
                acc1[q] += fmaxf(u1 + v, 0.f) * ae;
            }
        }
        #pragma unroll
        for (int q = 0; q < 4; ++q) {
            int jl = tj * 4 + q;
            sE[ti * 257 + j0 + jl]        = acc0[q] + sAI[ti]      + sAJ[jl];
            sE[(ti + 16) * 257 + j0 + jl] = acc1[q] + sAI[ti + 16] + sAJ[jl];
        }
    }
    __syncthreads();

    // softmax over j (256) per row; 8 warps x 4 rows
    const int warp = t >> 5, lane = t & 31;
    for (int r = warp; r < 32; r += 8) {
        const int gi = b * KF + i0 + r;
        float v[8];
        float m = -1e30f;
        #pragma unroll
        for (int q = 0; q < 8; ++q) {
            v[q] = sE[r * 257 + lane + q * 32] + ab[(size_t)(i0 + r) * KF + lane + q * 32];
            m = fmaxf(m, v[q]);
        }
        #pragma unroll
        for (int off = 16; off; off >>= 1) m = fmaxf(m, __shfl_xor_sync(0xffffffffu, m, off));
        float ssum = 0.f;
        #pragma unroll
        for (int q = 0; q < 8; ++q) { v[q] = __expf(v[q] - m); ssum += v[q]; }
        #pragma unroll
        for (int off = 16; off; off >>= 1) ssum += __shfl_xor_sync(0xffffffffu, ssum, off);
        float inv = 1.0f / ssum;
        #pragma unroll
        for (int q = 0; q < 8; ++q)
            g_ATT[(size_t)gi * KF + lane + q * 32] = v[q] * inv;
    }
}

// ============================================================================
// Kernel C: out[b,w,i] = sigmoid(sum_j ATT[b,i,j] * x[b,w,j])
// Block: (i-tile 64, w-tile 64, b). 256 threads, 4(w) x 4(i) micro, j tiled 64.
// ============================================================================
__global__ __launch_bounds__(256, 1)
void kernC(const float* __restrict__ x, float* __restrict__ out)
{
    __shared__ float sAtt[64 * 65];
    __shared__ float sX[64 * 65];

    const int b  = blockIdx.z;
    const int w0 = blockIdx.y * 64;
    const int i0 = blockIdx.x * 64;
    const int t  = threadIdx.x;
    const int tiv = t & 15;   // i group
    const int twv = t >> 4;   // w group

    float acc[4][4] = {};

    for (int jt = 0; jt < 4; ++jt) {
        __syncthreads();
        const int j0 = jt * 64;
        for (int idx = t; idx < 64 * 64; idx += 256) {
            int r = idx >> 6, c = idx & 63;
            sAtt[r * 65 + c] = g_ATT[((size_t)b * KF + i0 + r) * KF + j0 + c];
            sX[r * 65 + c]   = x[((size_t)b * WIN + w0 + r) * KF + j0 + c];
        }
        __syncthreads();

        #pragma unroll 4
        for (int jl = 0; jl < 64; ++jl) {
            float xv[4], av[4];
            #pragma unroll
            for (int p = 0; p < 4; ++p) xv[p] = sX[(twv + p * 16) * 65 + jl];
            #pragma unroll
            for (int q = 0; q < 4; ++q) av[q] = sAtt[(tiv + q * 16) * 65 + jl];
            #pragma unroll
            for (int p = 0; p < 4; ++p)
                #pragma unroll
                for (int q = 0; q < 4; ++q)
                    acc[p][q] += xv[p] * av[q];
        }
    }

    #pragma unroll
    for (int p = 0; p < 4; ++p) {
        int w = w0 + twv + p * 16;
        #pragma unroll
        for (int q = 0; q < 4; ++q) {
            int i = i0 + tiv + q * 16;
            float h = 1.0f / (1.0f + __expf(-acc[p][q]));
            out[((size_t)b * WIN + w) * KF + i] = h;
        }
    }
}

// ============================================================================
extern "C" void kernel_launch(void* const* d_in, const int* in_sizes, int n_in,
                              void* d_out, int out_size)
{
    const float* x   = (const float*)d_in[0];   // (16,128,256)
    const float* lw  = (const float*)d_in[1];   // (256,256)
    const float* lb  = (const float*)d_in[2];   // (256)
    const float* a   = (const float*)d_in[3];   // (256)
    const float* ab  = (const float*)d_in[4];   // (256,256)
    float* out = (float*)d_out;                 // (16,128,256)

    const int smemA = (128 * 64 + 64 * 128 + 64 * 128) * 4;                 // 96 KB
    const int smemB = (32 * 257 + 64 * 257 + 32 * 257 + 256 + 32 + 64) * 4; // ~130 KB

    static bool attr_set = false;
    // idempotent, not a stream op: safe under graph capture and deterministic
    cudaFuncSetAttribute(gemmA, cudaFuncAttributeMaxDynamicSharedMemorySize, smemA);
    cudaFuncSetAttribute(kernB, cudaFuncAttributeMaxDynamicSharedMemorySize, smemB);
    (void)attr_set;

    gemmA<<<dim3(4, 4, NB), 256, smemA>>>(x, lw, lb);
    dotAK<<<(2 * NB * KF) / 8, 256>>>(a);            // 8 warps/block -> 1024 blocks
    kernB<<<dim3(8, NB), 256, smemB>>>(a, ab);
    kernC<<<dim3(4, 2, NB), 256>>>(x, out);
}

// round 2
// speedup vs baseline: 1.3209x; 1.3209x over previous
#include <cuda_runtime.h>

#define NB   16
#define WIN  128
#define KF   256
#define EMB  256

typedef unsigned long long u64;

// ---- packed f32x2 helpers (sm_100+) ----------------------------------------
#define ADD2(d, a, b) asm("add.rn.f32x2 %0, %1, %2;" : "=l"(d) : "l"(a), "l"(b))
#define FMA2(d, a, b, c) asm("fma.rn.f32x2 %0, %1, %2, %3;" : "=l"(d) : "l"(a), "l"(b), "l"(c))
#define UNPK(lo, hi, v) asm("mov.b64 {%0, %1}, %2;" : "=f"(lo), "=f"(hi) : "l"(v))
#define PK(d, lo, hi) asm("mov.b64 %0, {%1, %2};" : "=l"(d) : "f"(lo), "f"(hi))

// ---------------- device scratch --------------------------------------------
__device__ float g_UI[NB * KF * EMB];   // hi + lin_b
__device__ float g_HJ[NB * KF * EMB];   // hj
__device__ float g_AI[NB * KF];         // 0.2 * dot(UI_row, a)
__device__ float g_AJ[NB * KF];         // 0.2 * dot(HJ_row, a)
__device__ float g_ATT[NB * KF * KF];   // e-matrix, then softmaxed in place

// ============================================================================
// gemmA: UI[b,k,e] = sum_w x[b,w,k]*W1[e,w] + lb[e];  HJ = sum_w x*W2
// 64k x 64e tile, f32x2 packed over w, smem-staged coalesced epilogue.
// ============================================================================
#define XP 130   // sXT pitch (floats): even, 130%32=2 -> conflict-free
__global__ __launch_bounds__(256)
void gemmA(const float* __restrict__ x, const float* __restrict__ lw,
           const float* __restrict__ lb)
{
    extern __shared__ float sm[];
    float* sXT = sm;                  // [64 k][130]  (w along row)
    float* sW1 = sXT + 64 * XP;       // [64 e][128 w]
    float* sW2 = sW1 + 64 * 128;      // [64 e][128 w]

    const int b  = blockIdx.z;
    const int kt = blockIdx.y * 64;
    const int et = blockIdx.x * 64;
    const int t  = threadIdx.x;

    const float* xb = x + (size_t)b * WIN * KF;
    for (int idx = t; idx < 128 * 64; idx += 256) {
        int w = idx >> 6, kk = idx & 63;
        sXT[kk * XP + w] = xb[w * KF + kt + kk];
    }
    for (int idx = t; idx < 64 * 128; idx += 256) {
        int ee = idx >> 7, w = idx & 127;
        sW1[idx] = lw[(et + ee) * (2 * WIN) + w];
        sW2[idx] = lw[(et + ee) * (2 * WIN) + WIN + w];
    }
    __syncthreads();

    const int tk = t & 15;   // k rows: tk + ii*16
    const int te = t >> 4;   // e rows: te + jj*16
    const u64* xp[4];  const u64* w1p[4];  const u64* w2p[4];
    #pragma unroll
    for (int ii = 0; ii < 4; ++ii) xp[ii] = (const u64*)(sXT + (tk + ii * 16) * XP);
    #pragma unroll
    for (int jj = 0; jj < 4; ++jj) {
        w1p[jj] = (const u64*)(sW1 + (te + jj * 16) * 128);
        w2p[jj] = (const u64*)(sW2 + (te + jj * 16) * 128);
    }

    u64 accI[4][4], accJ[4][4];
    #pragma unroll
    for (int ii = 0; ii < 4; ++ii)
        #pragma unroll
        for (int jj = 0; jj < 4; ++jj) { accI[ii][jj] = 0ull; accJ[ii][jj] = 0ull; }

    #pragma unroll 2
    for (int w = 0; w < 64; ++w) {            // w-pairs
        u64 xv[4], a1[4], a2[4];
        #pragma unroll
        for (int ii = 0; ii < 4; ++ii) xv[ii] = xp[ii][w];
        #pragma unroll
        for (int jj = 0; jj < 4; ++jj) { a1[jj] = w1p[jj][w]; a2[jj] = w2p[jj][w]; }
        #pragma unroll
        for (int ii = 0; ii < 4; ++ii)
            #pragma unroll
            for (int jj = 0; jj < 4; ++jj) {
                FMA2(accI[ii][jj], xv[ii], a1[jj], accI[ii][jj]);
                FMA2(accJ[ii][jj], xv[ii], a2[jj], accJ[ii][jj]);
            }
    }

    // ---- staged, coalesced epilogue (UI then HJ) ----
    float* sO = sm;                   // reuse sXT region (16.9KB < 33KB)
    __syncthreads();
    #pragma unroll
    for (int ii = 0; ii < 4; ++ii)
        #pragma unroll
        for (int jj = 0; jj < 4; ++jj) {
            float lo, hi; UNPK(lo, hi, accI[ii][jj]);
            sO[(tk + ii * 16) * 66 + te + jj * 16] = lo + hi + lb[et + te + jj * 16];
        }
    __syncthreads();
    for (int idx = t; idx < 64 * 64; idx += 256) {
        int r = idx >> 6, c = idx & 63;
        g_UI[((size_t)b * KF + kt + r) * EMB + et + c] = sO[r * 66 + c];
    }
    __syncthreads();
    #pragma unroll
    for (int ii = 0; ii < 4; ++ii)
        #pragma unroll
        for (int jj = 0; jj < 4; ++jj) {
            float lo, hi; UNPK(lo, hi, accJ[ii][jj]);
            sO[(tk + ii * 16) * 66 + te + jj * 16] = lo + hi;
        }
    __syncthreads();
    for (int idx = t; idx < 64 * 64; idx += 256) {
        int r = idx >> 6, c = idx & 63;
        g_HJ[((size_t)b * KF + kt + r) * EMB + et + c] = sO[r * 66 + c];
    }
}

// ============================================================================
// dotAK: AI[b,k] = 0.2*dot(UI[b,k,:],a); AJ likewise for HJ. One warp/row.
// ============================================================================
__global__ __launch_bounds__(256)
void dotAK(const float* __restrict__ a)
{
    int gw   = (blockIdx.x * blockDim.x + threadIdx.x) >> 5;
    int lane = threadIdx.x & 31;
    int which = gw / (NB * KF);
    int rk    = gw - which * (NB * KF);
    const float* row = (which ? g_HJ : g_UI) + (size_t)rk * EMB;
    float s = 0.f;
    #pragma unroll
    for (int q = 0; q < 8; ++q) s += row[lane + q * 32] * a[lane + q * 32];
    #pragma unroll
    for (int off = 16; off; off >>= 1) s += __shfl_xor_sync(0xffffffffu, s, off);
    if (lane == 0) (which ? g_AJ : g_AI)[rk] = 0.2f * s;
}

// ============================================================================
// kernB: e[b,i,j] = AI+AJ + sum_e relu(UI+HJ)*0.8a + attn_bias  -> g_ATT (raw)
// i-tile 32, j-tile 64, 512 blocks, 2 CTAs/SM. f32x2 packed over e.
// ============================================================================
#define BP 258   // smem pitch: even (8B rows), 258%32=2 -> conflict-free
__global__ __launch_bounds__(256)
void kernB(const float* __restrict__ a, const float* __restrict__ ab)
{
    extern __shared__ float sm[];
    float* sUI = sm;                   // [32][258]
    float* sHJ = sUI + 32 * BP;        // [64][258]
    float* sA8 = sHJ + 64 * BP;        // [256]
    float* sAI = sA8 + 256;            // [32]
    float* sAJ = sAI + 32;             // [64]

    const int b  = blockIdx.z;
    const int i0 = blockIdx.y * 32;
    const int j0 = blockIdx.x * 64;
    const int t  = threadIdx.x;

    const float4* gu = (const float4*)(g_UI + ((size_t)b * KF + i0) * EMB);
    for (int idx = t; idx < 32 * 64; idx += 256) {
        int r = idx >> 6, c = idx & 63;
        float4 v = gu[r * 64 + c];
        float2* d = (float2*)(sUI + r * BP + c * 4);
        d[0] = make_float2(v.x, v.y); d[1] = make_float2(v.z, v.w);
    }
    const float4* gh = (const float4*)(g_HJ + ((size_t)b * KF + j0) * EMB);
    for (int idx = t; idx < 64 * 64; idx += 256) {
        int r = idx >> 6, c = idx & 63;
        float4 v = gh[r * 64 + c];
        float2* d = (float2*)(sHJ + r * BP + c * 4);
        d[0] = make_float2(v.x, v.y); d[1] = make_float2(v.z, v.w);
    }
    sA8[t] = 0.8f * a[t];
    if (t < 32) sAI[t] = g_AI[b * KF + i0 + t];
    else if (t < 96) sAJ[t - 32] = g_AJ[b * KF + j0 + t - 32];
    __syncthreads();

    const int ti = t >> 4;   // i rows: ti, ti+16
    const int jl = t & 15;   // j cols: jl + q*16
    const u64* u0p = (const u64*)(sUI + ti * BP);
    const u64* u1p = (const u64*)(sUI + (ti + 16) * BP);
    const u64* vp[4];
    #pragma unroll
    for (int q = 0; q < 4; ++q) vp[q] = (const u64*)(sHJ + (jl + q * 16) * BP);
    const u64* ap = (const u64*)sA8;

    u64 acc0[4], acc1[4];
    #pragma unroll
    for (int q = 0; q < 4; ++q) { acc0[q] = 0ull; acc1[q] = 0ull; }

    #pragma unroll 2
    for (int e = 0; e < 128; ++e) {          // e-pairs
        u64 ae = ap[e], u0 = u0p[e], u1 = u1p[e];
        #pragma unroll
        for (int q = 0; q < 4; ++q) {
            u64 v = vp[q][e];
            u64 s0, s1;
            ADD2(s0, u0, v); ADD2(s1, u1, v);
            float x0, y0, x1, y1;
            UNPK(x0, y0, s0); UNPK(x1, y1, s1);
            x0 = fmaxf(x0, 0.f); y0 = fmaxf(y0, 0.f);
            x1 = fmaxf(x1, 0.f); y1 = fmaxf(y1, 0.f);
            u64 r0, r1; PK(r0, x0, y0); PK(r1, x1, y1);
            FMA2(acc0[q], r0, ae, acc0[q]);
            FMA2(acc1[q], r1, ae, acc1[q]);
        }
    }

    const float ai0 = sAI[ti], ai1 = sAI[ti + 16];
    #pragma unroll
    for (int q = 0; q < 4; ++q) {
        int jc = jl + q * 16;
        int j  = j0 + jc;
        float lo, hi;
        UNPK(lo, hi, acc0[q]);
        g_ATT[((size_t)b * KF + i0 + ti) * KF + j] =
            lo + hi + ai0 + sAJ[jc] + ab[(size_t)(i0 + ti) * KF + j];
        UNPK(lo, hi, acc1[q]);
        g_ATT[((size_t)b * KF + i0 + ti + 16) * KF + j] =
            lo + hi + ai1 + sAJ[jc] + ab[(size_t)(i0 + ti + 16) * KF + j];
    }
}

// ============================================================================
// kernSoft: in-place row softmax of g_ATT over j. One warp per row.
// ============================================================================
__global__ __launch_bounds__(256)
void kernSoft()
{
    const int row  = blockIdx.x * 8 + (threadIdx.x >> 5);
    const int lane = threadIdx.x & 31;
    float4* p = (float4*)(g_ATT + (size_t)row * KF);
    float4 v0 = p[lane], v1 = p[lane + 32];
    float m = fmaxf(fmaxf(fmaxf(v0.x, v0.y), fmaxf(v0.z, v0.w)),
                    fmaxf(fmaxf(v1.x, v1.y), fmaxf(v1.z, v1.w)));
    #pragma unroll
    for (int off = 16; off; off >>= 1) m = fmaxf(m, __shfl_xor_sync(0xffffffffu, m, off));
    v0.x = __expf(v0.x - m); v0.y = __expf(v0.y - m);
    v0.z = __expf(v0.z - m); v0.w = __expf(v0.w - m);
    v1.x = __expf(v1.x - m); v1.y = __expf(v1.y - m);
    v1.z = __expf(v1.z - m); v1.w = __expf(v1.w - m);
    float s = v0.x + v0.y + v0.z + v0.w + v1.x + v1.y + v1.z + v1.w;
    #pragma unroll
    for (int off = 16; off; off >>= 1) s += __shfl_xor_sync(0xffffffffu, s, off);
    float inv = 1.0f / s;
    v0.x *= inv; v0.y *= inv; v0.z *= inv; v0.w *= inv;
    v1.x *= inv; v1.y *= inv; v1.z *= inv; v1.w *= inv;
    p[lane] = v0; p[lane + 32] = v1;
}

// ============================================================================
// kernC: out[b,w,i] = sigmoid(sum_j ATT[b,i,j] * x[b,w,j])
// i-tile 64, w-tile 32, 256 blocks. f32x2 packed over j.
// ============================================================================
#define CP 66    // pitch: even, 66%32=2 -> conflict-free
__global__ __launch_bounds__(256)
void kernC(const float* __restrict__ x, float* __restrict__ out)
{
    __shared__ float sAtt[64 * CP];
    __shared__ float sX[32 * CP];

    const int b  = blockIdx.z;
    const int w0 = blockIdx.y * 32;
    const int i0 = blockIdx.x * 64;
    const int t  = threadIdx.x;
    const int il = t & 15;   // i: il + qi*16
    const int tw = t >> 4;   // w: tw, tw+16

    u64 acc[4][2];
    #pragma unroll
    for (int qi = 0; qi < 4; ++qi) { acc[qi][0] = 0ull; acc[qi][1] = 0ull; }

    for (int jt = 0; jt < 4; ++jt) {
        __syncthreads();
        const int j0 = jt * 64;
        for (int idx = t; idx < 64 * 16; idx += 256) {
            int r = idx >> 4, c = idx & 15;
            float4 v = *(const float4*)(g_ATT + ((size_t)b * KF + i0 + r) * KF + j0 + c * 4);
            float2* d = (float2*)(sAtt + r * CP + c * 4);
            d[0] = make_float2(v.x, v.y); d[1] = make_float2(v.z, v.w);
        }
        for (int idx = t; idx < 32 * 16; idx += 256) {
            int r = idx >> 4, c = idx & 15;
            float4 v = *(const float4*)(x + ((size_t)b * WIN + w0 + r) * KF + j0 + c * 4);
            float2* d = (float2*)(sX + r * CP + c * 4);
            d[0] = make_float2(v.x, v.y); d[1] = make_float2(v.z, v.w);
        }
        __syncthreads();

        const u64* xp0 = (const u64*)(sX + tw * CP);
        const u64* xp1 = (const u64*)(sX + (tw + 16) * CP);
        const u64* avp[4];
        #pragma unroll
        for (int qi = 0; qi < 4; ++qi) avp[qi] = (const u64*)(sAtt + (il + qi * 16) * CP);

        #pragma unroll 4
        for (int j = 0; j < 32; ++j) {       // j-pairs
            u64 x0 = xp0[j], x1 = xp1[j];
            #pragma unroll
            for (int qi = 0; qi < 4; ++qi) {
                u64 av = avp[qi][j];
                FMA2(acc[qi][0], av, x0, acc[qi][0]);
                FMA2(acc[qi][1], av, x1, acc[qi][1]);
            }
        }
    }

    #pragma unroll
    for (int qi = 0; qi < 4; ++qi) {
        int i = i0 + il + qi * 16;
        #pragma unroll
        for (int qw = 0; qw < 2; ++qw) {
            int w = w0 + tw + qw * 16;
            float lo, hi; UNPK(lo, hi, acc[qi][qw]);
            float s = lo + hi;
            out[((size_t)b * WIN + w) * KF + i] = 1.0f / (1.0f + __expf(-s));
        }
    }
}

// ============================================================================
extern "C" void kernel_launch(void* const* d_in, const int* in_sizes, int n_in,
                              void* d_out, int out_size)
{
    const float* x   = (const float*)d_in[0];   // (16,128,256)
    const float* lw  = (const float*)d_in[1];   // (256,256)
    const float* lb  = (const float*)d_in[2];   // (256)
    const float* a   = (const float*)d_in[3];   // (256)
    const float* ab  = (const float*)d_in[4];   // (256,256)
    float* out = (float*)d_out;                 // (16,128,256)

    const int smemA = (64 * XP + 64 * 128 + 64 * 128) * 4;           // ~96.6 KB
    const int smemB = (32 * BP + 64 * BP + 256 + 32 + 64) * 4;       // ~98.1 KB

    cudaFuncSetAttribute(gemmA, cudaFuncAttributeMaxDynamicSharedMemorySize, smemA);
    cudaFuncSetAttribute(kernB, cudaFuncAttributeMaxDynamicSharedMemorySize, smemB);

    gemmA<<<dim3(4, 4, NB), 256, smemA>>>(x, lw, lb);
    dotAK<<<(2 * NB * KF) / 8, 256>>>(a);
    kernB<<<dim3(4, 8, NB), 256, smemB>>>(a, ab);
    kernSoft<<<(NB * KF) / 8, 256>>>();
    kernC<<<dim3(4, 4, NB), 256>>>(x, out);
}